// round 7
// baseline (speedup 1.0000x reference)
#include <cuda_runtime.h>

// Problem constants (SLEN=208, PTILE=8, STEP=2, EDGE=3, MAXDET=2)
#define BATCH 16
#define NSRC  100
#define NFLUX 5
#define NT    101                 // tiles per dim
#define PT    (NT * NT)           // 10201
#define BP    (BATCH * PT)        // 163216
// Output sections (float32, concatenated):
//   n [BP] | locs [BP*4] | fluxes [BP*10] | is_on [BP*2]
#define OFF_L (BP)                 // 163216  (mult of 4)
#define OFF_F (OFF_L + BP * 4)     // 816080  (mult of 4)
#define OFF_I (OFF_F + BP * 10)    // 2448240 (mult of 4)

#define TPB    256
#define CHUNK  276                         // mult of 4, < PT (spans <= 2 batches)
#define GRID   ((BP + CHUNK - 1) / CHUNK)  // 592 = 4 blocks/SM, single wave
#define MAXLOC 256

// Map pixel coords -> (tile, fx, fy); returns tile or -1. Bit-identical to R1.
__device__ __forceinline__ int map_source(float l0, float l1, float& fx, float& fy) {
    float p0 = l0 * 207.0f;                                  // SLEN-1
    float p1 = l1 * 207.0f;
    int kx = (int)floorf((p0 - 2.5f) * 0.5f);
    int ky = (int)floorf((p1 - 2.5f) * 0.5f);
    float lx = 2.0f * (float)kx + 2.5f;                      // exact fp32
    float ly = 2.0f * (float)ky + 2.5f;
    bool v0 = (kx >= 0) && (kx < NT) && (p0 > lx) && (p0 < lx + 2.0f) && (p0 != 0.0f);
    bool v1 = (ky >= 0) && (ky < NT) && (p1 > ly) && (p1 < ly + 2.0f) && (p1 != 0.0f);
    if (!(v0 && v1)) return -1;
    fx = (p0 - lx) * 0.5f;                                   // (lp - left)/scale, exact
    fy = (p1 - ly) * 0.5f;
    return kx * NT + ky;
}

__global__ __launch_bounds__(TPB)
void fused_kernel(const float* __restrict__ locs,
                  const float* __restrict__ fluxes,
                  float* __restrict__ out) {
    __shared__ int     s_cnt;
    __shared__ int     s_ent[MAXLOC];          // (cell_local << 11) | idx
    __shared__ float   s_fx[MAXLOC];
    __shared__ float   s_fy[MAXLOC];
    __shared__ float   s_flux[MAXLOC][NFLUX];
    __shared__ short   s_slot0[CHUNK];         // entry id for rank 0, or -1
    __shared__ short   s_slot1[CHUNK];         // entry id for rank 1, or -1
    __shared__ unsigned char s_ncap[CHUNK];    // min(count, 2)

    const int t  = threadIdx.x;
    const int g0 = blockIdx.x * CHUNK;
    const int g1 = min(g0 + CHUNK, BP);
    const int n  = g1 - g0;                    // multiple of 4

    // ---- front-issue the source load (L2 latency overlaps shared init) ----
    const int b_lo  = g0 / PT;
    const int b_hi  = (g1 - 1) / PT;           // <= b_lo + 1
    const int i_lo  = b_lo * NSRC;
    const int span  = (b_hi + 1) * NSRC - i_lo;    // <= 200 <= TPB
    const int idx   = i_lo + t;
    const bool has  = (t < span);
    float2 l = make_float2(0.f, 0.f);
    if (has) l = __ldg(&((const float2*)locs)[idx]);

    if (t == 0) s_cnt = 0;
    // init slot tables (needed before publish phase, i.e. before B2 suffices,
    // but s_cnt must precede Phase B atomics -> one barrier covers both)
    if (t < CHUNK)       { s_slot0[t] = -1; s_slot1[t] = -1; s_ncap[t] = 0; }
    if (t + TPB < CHUNK) { s_slot0[t + TPB] = -1; s_slot1[t + TPB] = -1; s_ncap[t + TPB] = 0; }
    __syncthreads();                                           // B1 (shared only)

    // ---- Phase B: classify my source, append to local list, prefetch flux ----
    if (has) {
        float fx, fy;
        int tile = map_source(l.x, l.y, fx, fy);
        if (tile >= 0) {
            int g = (idx / NSRC) * PT + tile;
            if (g >= g0 && g < g1) {
                int pos = atomicAdd(&s_cnt, 1);
                s_ent[pos] = ((g - g0) << 11) | idx;
                s_fx[pos]  = fx;
                s_fy[pos]  = fy;
                const float* __restrict__ fl = fluxes + idx * NFLUX;
                #pragma unroll
                for (int j = 0; j < NFLUX; j++) s_flux[pos][j] = __ldg(&fl[j]);
            }
        }
    }
    __syncthreads();                                           // B2 (shared only)

    // ---- rank within tiny list, publish per-cell slot table ----
    const int cnt = s_cnt;
    if (t < cnt) {
        const int ent  = s_ent[t];
        const int c    = ent >> 11;
        const int sidx = ent & 2047;
        int count = 0, rank = 0;
        for (int j = 0; j < cnt; j++) {
            int o = s_ent[j];
            if ((o >> 11) == c) { count++; if ((o & 2047) < sidx) rank++; }
        }
        if (rank == 0) s_ncap[c] = (unsigned char)(count < 2 ? count : 2);
        if (rank == 0) s_slot0[c] = (short)t;
        if (rank == 1) s_slot1[c] = (short)t;
    }
    __syncthreads();                                           // B3 (shared only)

    // ---- single merged fill: every output byte written exactly once ----
    const float4 z = make_float4(0.f, 0.f, 0.f, 0.f);

    // n-section: 1 float per cell, n/4 float4
    {
        float4* __restrict__ pN = (float4*)(out + g0);
        const int cN = n >> 2;                 // <= 69: single predicated iter
        if (t < cN) {
            int c = 4 * t;
            pN[t] = make_float4((float)s_ncap[c], (float)s_ncap[c + 1],
                                (float)s_ncap[c + 2], (float)s_ncap[c + 3]);
        }
    }
    // locs-section: exactly 1 float4 per cell
    {
        float4* __restrict__ pL = (float4*)(out + OFF_L + 4 * g0);
        for (int c = t; c < n; c += TPB) {     // <= 2 iters
            int e0 = s_slot0[c], e1 = s_slot1[c];
            float4 v = z;
            if (e0 >= 0) { v.x = s_fx[e0]; v.y = s_fy[e0]; }
            if (e1 >= 0) { v.z = s_fx[e1]; v.w = s_fy[e1]; }
            pL[c] = v;
        }
    }
    // flux-section: 10 floats per cell, (10n)/4 float4
    {
        float4* __restrict__ pF = (float4*)(out + OFF_F + 10 * g0);
        const int cF = (10 * n) >> 2;          // <= 690: 3 iters
        for (int f = t; f < cF; f += TPB) {
            float v[4];
            #pragma unroll
            for (int j = 0; j < 4; j++) {
                unsigned pos = 4u * f + j;
                unsigned c   = pos / 10u;
                unsigned o   = pos - 10u * c;      // 0..9
                int e = (o < 5u) ? (int)s_slot0[c] : (int)s_slot1[c];
                unsigned k = (o < 5u) ? o : o - 5u;
                v[j] = (e >= 0) ? s_flux[e][k] : 0.f;
            }
            pF[f] = make_float4(v[0], v[1], v[2], v[3]);
        }
    }
    // is_on-section: 2 floats per cell, n/2 float4
    {
        float4* __restrict__ pI = (float4*)(out + OFF_I + 2 * g0);
        const int cI = n >> 1;                 // <= 138: single predicated iter
        if (t < cI) {
            int c = 2 * t;
            pI[t] = make_float4(s_slot0[c]     >= 0 ? 1.f : 0.f,
                                s_slot1[c]     >= 0 ? 1.f : 0.f,
                                s_slot0[c + 1] >= 0 ? 1.f : 0.f,
                                s_slot1[c + 1] >= 0 ? 1.f : 0.f);
        }
    }
}

extern "C" void kernel_launch(void* const* d_in, const int* in_sizes, int n_in,
                              void* d_out, int out_size) {
    const float* locs   = (const float*)d_in[0];   // (16, 100, 2) f32
    const float* fluxes = (const float*)d_in[1];   // (16, 100, 5) f32
    fused_kernel<<<GRID, TPB>>>(locs, fluxes, (float*)d_out);
}

// round 8
// speedup vs baseline: 1.1071x; 1.1071x over previous
#include <cuda_runtime.h>

// Problem constants (SLEN=208, PTILE=8, STEP=2, EDGE=3, MAXDET=2)
#define BATCH 16
#define NSRC  100
#define NFLUX 5
#define NT    101                 // tiles per dim
#define PT    (NT * NT)           // 10201
#define BP    (BATCH * PT)        // 163216
// Output sections (float32, concatenated):
//   n [BP] | locs [BP*4] | fluxes [BP*10] | is_on [BP*2]
#define OFF_L (BP)                 // 163216  (mult of 4)
#define OFF_F (OFF_L + BP * 4)     // 816080  (mult of 4)
#define OFF_I (OFF_F + BP * 10)    // 2448240 (mult of 4)

#define TPB    1024
#define CHUNK  1104                        // mult of 4, < PT (spans <= 2 batches)
#define GRID   ((BP + CHUNK - 1) / CHUNK)  // 148: one block per SM, single wave
#define MAXLOC 256

// Map pixel coords -> (tile, fx, fy); returns tile or -1. Bit-identical to R1.
__device__ __forceinline__ int map_source(float l0, float l1, float& fx, float& fy) {
    float p0 = l0 * 207.0f;                                  // SLEN-1
    float p1 = l1 * 207.0f;
    int kx = (int)floorf((p0 - 2.5f) * 0.5f);
    int ky = (int)floorf((p1 - 2.5f) * 0.5f);
    float lx = 2.0f * (float)kx + 2.5f;                      // exact fp32
    float ly = 2.0f * (float)ky + 2.5f;
    bool v0 = (kx >= 0) && (kx < NT) && (p0 > lx) && (p0 < lx + 2.0f) && (p0 != 0.0f);
    bool v1 = (ky >= 0) && (ky < NT) && (p1 > ly) && (p1 < ly + 2.0f) && (p1 != 0.0f);
    if (!(v0 && v1)) return -1;
    fx = (p0 - lx) * 0.5f;                                   // (lp - left)/scale, exact
    fy = (p1 - ly) * 0.5f;
    return kx * NT + ky;
}

__global__ __launch_bounds__(TPB)
void fused_kernel(const float* __restrict__ locs,
                  const float* __restrict__ fluxes,
                  float* __restrict__ out) {
    __shared__ int   s_cnt;
    __shared__ int   s_ent[MAXLOC];   // (g << 11) | idx
    __shared__ float s_fx[MAXLOC];
    __shared__ float s_fy[MAXLOC];
    __shared__ float s_flux[MAXLOC][NFLUX];

    const int t  = threadIdx.x;
    const int g0 = blockIdx.x * CHUNK;
    const int g1 = min(g0 + CHUNK, BP);
    const int n  = g1 - g0;           // multiple of 4

    // ---- front-issue ALL input loads (locs + flux), L2 latency overlaps fill ----
    const int b_lo  = g0 / PT;
    const int b_hi  = (g1 - 1) / PT;              // <= b_lo + 1
    const int i_lo  = b_lo * NSRC;
    const int span  = (b_hi + 1) * NSRC - i_lo;   // <= 200 <= TPB
    const int idx   = i_lo + t;
    const bool has  = (t < span);
    float2 l = make_float2(0.f, 0.f);
    float fv0 = 0.f, fv1 = 0.f, fv2 = 0.f, fv3 = 0.f, fv4 = 0.f;
    if (has) {
        l = __ldg(&((const float2*)locs)[idx]);
        const float* __restrict__ fl = fluxes + idx * NFLUX;
        fv0 = __ldg(fl + 0); fv1 = __ldg(fl + 1); fv2 = __ldg(fl + 2);
        fv3 = __ldg(fl + 3); fv4 = __ldg(fl + 4);
    }

    if (t == 0) s_cnt = 0;

    // ---- Phase A: zero the 4 per-section slices; <=7 predicated STG.128 ----
    {
        const float4 z = make_float4(0.f, 0.f, 0.f, 0.f);
        float4* __restrict__ pN = (float4*)(out + g0);
        float4* __restrict__ pL = (float4*)(out + OFF_L + 4  * g0);
        float4* __restrict__ pF = (float4*)(out + OFF_F + 10 * g0);
        float4* __restrict__ pI = (float4*)(out + OFF_I + 2  * g0);
        const int cN = n >> 2;          // <= 276
        const int cL = n;               // <= 1104
        const int cF = (10 * n) >> 2;   // <= 2760
        const int cI = n >> 1;          // <= 552
        if (t           < cN) pN[t]           = z;
        if (t           < cL) pL[t]           = z;
        if (t + TPB     < cL) pL[t + TPB]     = z;
        if (t           < cF) pF[t]           = z;
        if (t + TPB     < cF) pF[t + TPB]     = z;
        if (t + 2 * TPB < cF) pF[t + 2 * TPB] = z;
        if (t           < cI) pI[t]           = z;
    }
    __syncthreads();   // s_cnt=0 visible before atomics

    // ---- Phase B: classify my (already-loaded) source, park payload in shared ----
    if (has) {
        float fx, fy;
        int tile = map_source(l.x, l.y, fx, fy);
        if (tile >= 0) {
            int g = (idx / NSRC) * PT + tile;
            if (g >= g0 && g < g1) {
                int pos = atomicAdd(&s_cnt, 1);
                s_ent[pos] = (g << 11) | idx;
                s_fx[pos]  = fx;
                s_fy[pos]  = fy;
                s_flux[pos][0] = fv0; s_flux[pos][1] = fv1; s_flux[pos][2] = fv2;
                s_flux[pos][3] = fv3; s_flux[pos][4] = fv4;
            }
        }
    }
    __syncthreads();   // orders Phase-A stores before Phase-C stores (CTA scope)

    // ---- Phase C: rank within tiny local list (~dozens), write payloads ----
    const int cnt = s_cnt;
    if (t < cnt) {
        const int ent  = s_ent[t];
        const int g    = ent >> 11;
        const int sidx = ent & 2047;

        int count = 0, rank = 0;
        for (int j = 0; j < cnt; j++) {
            int o = s_ent[j];
            if ((o >> 11) == g) {
                count++;
                if ((o & 2047) < sidx) rank++;
            }
        }

        if (rank == 0)
            out[g] = (float)(count < 2 ? count : 2);     // min(n, MAXDET)

        if (rank < 2) {
            *(float2*)(out + OFF_L + 4 * g + 2 * rank) = make_float2(s_fx[t], s_fy[t]);

            int fb = OFF_F + 10 * g + 5 * rank;
            out[fb + 0] = s_flux[t][0];
            out[fb + 1] = s_flux[t][1];
            out[fb + 2] = s_flux[t][2];
            out[fb + 3] = s_flux[t][3];
            out[fb + 4] = s_flux[t][4];

            out[OFF_I + 2 * g + rank] = 1.0f;
        }
    }
}

extern "C" void kernel_launch(void* const* d_in, const int* in_sizes, int n_in,
                              void* d_out, int out_size) {
    const float* locs   = (const float*)d_in[0];   // (16, 100, 2) f32
    const float* fluxes = (const float*)d_in[1];   // (16, 100, 5) f32
    fused_kernel<<<GRID, TPB>>>(locs, fluxes, (float*)d_out);
}

// round 9
// speedup vs baseline: 1.3478x; 1.2174x over previous
#include <cuda_runtime.h>

// Problem constants (SLEN=208, PTILE=8, STEP=2, EDGE=3, MAXDET=2)
#define BATCH 16
#define NSRC  100
#define NFLUX 5
#define NT    101                 // tiles per dim
#define PT    (NT * NT)           // 10201
#define BP    (BATCH * PT)        // 163216
// Output sections (float32, concatenated):
//   n [BP] | locs [BP*4] | fluxes [BP*10] | is_on [BP*2]
#define OFF_L (BP)                 // 163216  (mult of 4)
#define OFF_F (OFF_L + BP * 4)     // 816080  (mult of 4)
#define OFF_I (OFF_F + BP * 10)    // 2448240 (mult of 4)

#define TPB    256
#define NWARP  (TPB / 32)
#define CHUNK  276                         // mult of 4, < PT (spans <= 2 batches)
#define GRID   ((BP + CHUNK - 1) / CHUNK)  // 592: 4 blocks/SM, single wave

// Map pixel coords -> (tile, fx, fy); returns tile or -1. Bit-identical to R1.
__device__ __forceinline__ int map_source(float l0, float l1, float& fx, float& fy) {
    float p0 = l0 * 207.0f;                                  // SLEN-1
    float p1 = l1 * 207.0f;
    int kx = (int)floorf((p0 - 2.5f) * 0.5f);
    int ky = (int)floorf((p1 - 2.5f) * 0.5f);
    float lx = 2.0f * (float)kx + 2.5f;                      // exact fp32
    float ly = 2.0f * (float)ky + 2.5f;
    bool v0 = (kx >= 0) && (kx < NT) && (p0 > lx) && (p0 < lx + 2.0f) && (p0 != 0.0f);
    bool v1 = (ky >= 0) && (ky < NT) && (p1 > ly) && (p1 < ly + 2.0f) && (p1 != 0.0f);
    if (!(v0 && v1)) return -1;
    fx = (p0 - lx) * 0.5f;                                   // (lp - left)/scale, exact
    fy = (p1 - ly) * 0.5f;
    return kx * NT + ky;
}

__global__ __launch_bounds__(TPB)
void fused_kernel(const float* __restrict__ locs,
                  const float* __restrict__ fluxes,
                  float* __restrict__ out) {
    __shared__ int      s_g[TPB];       // cell id for slot t (valid iff mask bit set)
    __shared__ unsigned s_mask[NWARP];  // per-warp acceptance ballots

    const int t  = threadIdx.x;
    const int g0 = blockIdx.x * CHUNK;
    const int g1 = min(g0 + CHUNK, BP);
    const int n  = g1 - g0;             // multiple of 4

    // ---- front-issue ALL input loads; L2 latency overlaps the fill ----
    const int b_lo = g0 / PT;
    const int b_hi = (g1 - 1) / PT;                // <= b_lo + 1
    const int i_lo = b_lo * NSRC;
    const int span = (b_hi + 1) * NSRC - i_lo;     // <= 200 <= TPB
    const int idx  = i_lo + t;
    const bool has = (t < span);
    float2 l = make_float2(0.f, 0.f);
    float fv0 = 0.f, fv1 = 0.f, fv2 = 0.f, fv3 = 0.f, fv4 = 0.f;
    if (has) {
        l = __ldg(&((const float2*)locs)[idx]);
        const float* __restrict__ fl = fluxes + idx * NFLUX;
        fv0 = __ldg(fl + 0); fv1 = __ldg(fl + 1); fv2 = __ldg(fl + 2);
        fv3 = __ldg(fl + 3); fv4 = __ldg(fl + 4);
    }

    // ---- Phase A: zero the 4 per-section slices; <=7 predicated STG.128 ----
    {
        const float4 z = make_float4(0.f, 0.f, 0.f, 0.f);
        float4* __restrict__ pN = (float4*)(out + g0);
        float4* __restrict__ pL = (float4*)(out + OFF_L + 4  * g0);
        float4* __restrict__ pF = (float4*)(out + OFF_F + 10 * g0);
        float4* __restrict__ pI = (float4*)(out + OFF_I + 2  * g0);
        const int cN = n >> 2;          // <= 69
        const int cL = n;               // <= 276
        const int cF = (10 * n) >> 2;   // <= 690
        const int cI = n >> 1;          // <= 138
        if (t           < cN) pN[t]           = z;
        if (t           < cL) pL[t]           = z;
        if (t + TPB     < cL) pL[t + TPB]     = z;
        if (t           < cF) pF[t]           = z;
        if (t + TPB     < cF) pF[t + TPB]     = z;
        if (t + 2 * TPB < cF) pF[t + 2 * TPB] = z;
        if (t           < cI) pI[t]           = z;
    }

    // ---- Phase B: classify (no atomics, no counter). Slot = thread id. ----
    float fx = 0.f, fy = 0.f;
    int   g  = -1;
    if (has) {
        int tile = map_source(l.x, l.y, fx, fy);
        if (tile >= 0) {
            int b = b_lo + (t >= NSRC ? 1 : 0);    // idx/NSRC without divide
            int gg = b * PT + tile;
            if (gg >= g0 && gg < g1) g = gg;
        }
    }
    const bool acc = (g >= 0);
    unsigned m = __ballot_sync(0xFFFFFFFFu, acc);
    if ((t & 31) == 0) s_mask[t >> 5] = m;         // every warp publishes
    if (acc) s_g[t] = g;                           // only accepted slots are read

    __syncthreads();   // ONE barrier: shared visibility + zero/payload WAW order

    // ---- Phase C: rank by walking the ~14 mask bits; payload from registers ----
    if (acc) {
        int count = 0, rank = 0;
        #pragma unroll
        for (int w = 0; w < NWARP; w++) {
            unsigned mw = s_mask[w];
            while (mw) {
                int b  = __ffs(mw) - 1;
                mw &= mw - 1;
                int j  = (w << 5) + b;
                if (s_g[j] == g) { count++; rank += (j < t); }
            }
        }

        if (rank == 0)
            out[g] = (float)(count < 2 ? count : 2);     // min(n, MAXDET)

        if (rank < 2) {
            *(float2*)(out + OFF_L + 4 * g + 2 * rank) = make_float2(fx, fy);

            int fb = OFF_F + 10 * g + 5 * rank;
            out[fb + 0] = fv0;
            out[fb + 1] = fv1;
            out[fb + 2] = fv2;
            out[fb + 3] = fv3;
            out[fb + 4] = fv4;

            out[OFF_I + 2 * g + rank] = 1.0f;
        }
    }
}

extern "C" void kernel_launch(void* const* d_in, const int* in_sizes, int n_in,
                              void* d_out, int out_size) {
    const float* locs   = (const float*)d_in[0];   // (16, 100, 2) f32
    const float* fluxes = (const float*)d_in[1];   // (16, 100, 5) f32
    fused_kernel<<<GRID, TPB>>>(locs, fluxes, (float*)d_out);
}